// round 16
// baseline (speedup 1.0000x reference)
#include <cuda_runtime.h>
#include <cuda_fp16.h>
#include <cstdint>

#define NN 50000
#define DD 128
#define EE 800000
#define TD 384
#define MAXDEG 48
#define CAP 64
#define BN_BLOCKS 512
#define BN_CHUNK 98
#define GNODES 64
#define GRU_BLOCKS ((NN + GNODES - 1) / GNODES)   // 782
#define GEMM_CHUNKS ((NN + 31) / 32)              // 1563
#define GPERS 296
#define SORT_BLOCKS ((NN + 31) / 32)              // 1563

// ---------------- scratch (static device memory; no allocations) ----------------
__device__ float  g_X[NN * DD];
// G2 layout: [node][slice(8)][t4(4)][dt(2)][gate(3)][2 halves] = 384 halves/node
__device__ __half g_Gh[(size_t)NN * TD];
__device__ float  g_Hn[NN * DD];
__device__ float  g_part[2 * BN_BLOCKS * DD];
__device__ float  g_mu[DD];
__device__ float  g_scale[DD];
__device__ int    g_deg[NN];
__device__ unsigned long long g_keys[(size_t)NN * CAP];
__device__ int    g_neigh[NN * MAXDEG];
__device__ int    g_len[NN];
__device__ int    g_order[NN];
__device__ int    g_hist[MAXDEG + 1];
__device__ int    g_cnt[MAXDEG + 1];

// ---------------- helpers ----------------
__device__ __forceinline__ void mma16(float* c, const uint32_t* a, const uint32_t* b) {
    asm volatile(
        "mma.sync.aligned.m16n8k16.row.col.f32.f16.f16.f32 "
        "{%0,%1,%2,%3},{%4,%5,%6,%7},{%8,%9},{%0,%1,%2,%3};"
        : "+f"(c[0]), "+f"(c[1]), "+f"(c[2]), "+f"(c[3])
        : "r"(a[0]), "r"(a[1]), "r"(a[2]), "r"(a[3]), "r"(b[0]), "r"(b[1]));
}
__device__ __forceinline__ void ldsm4(uint32_t* r, uint32_t addr) {
    asm volatile("ldmatrix.sync.aligned.m8n8.x4.shared.b16 {%0,%1,%2,%3}, [%4];"
                 : "=r"(r[0]), "=r"(r[1]), "=r"(r[2]), "=r"(r[3]) : "r"(addr));
}
__device__ __forceinline__ uint32_t smem_u32(const void* p) {
    uint32_t a;
    asm("{ .reg .u64 t; cvta.to.shared.u64 t, %1; cvt.u32.u64 %0, t; }" : "=r"(a) : "l"(p));
    return a;
}
__device__ __forceinline__ uint32_t h2tanh(uint32_t x) {
    uint32_t y;
    asm("tanh.approx.f16x2 %0, %1;" : "=r"(y) : "r"(x));
    return y;
}
__device__ __forceinline__ uint32_t pack_h2(float a, float b) {
    __half2 h = __floats2half2_rn(a, b);
    return *(uint32_t*)&h;
}
__device__ __forceinline__ float2 unpack_h2(uint32_t u) {
    return __half22float2(*(__half2*)&u);
}

// ---------------- K1: BN partial sums + clear counters ----------------
__global__ void bn_clear_k(const float* __restrict__ feat) {
    int b = blockIdx.x, tid = threadIdx.x;
    if (b < BN_BLOCKS) {
        int r0 = b * BN_CHUNK;
        int r1 = r0 + BN_CHUNK; if (r1 > NN) r1 = NN;
        float s = 0.f, ss = 0.f;
        for (int r = r0; r < r1; r++) {
            float v = feat[(size_t)r * DD + tid];
            s += v; ss += v * v;
        }
        g_part[b * DD + tid] = s;
        g_part[BN_BLOCKS * DD + b * DD + tid] = ss;
    } else {
        int i = (b - BN_BLOCKS) * 128 + tid;
        if (i < NN) g_deg[i] = 0;
        if (i <= MAXDEG) { g_hist[i] = 0; g_cnt[i] = 0; }
    }
}

// ---------------- K2: BN finalize ----------------
__global__ void bn_final_k(const float* __restrict__ gamma) {
    int d = threadIdx.x;
    float s = 0.f, ss = 0.f;
    for (int b = 0; b < BN_BLOCKS; b++) {
        s  += g_part[b * DD + d];
        ss += g_part[BN_BLOCKS * DD + b * DD + d];
    }
    float mu = s / (float)NN;
    float var = ss / (float)NN - mu * mu;
    g_mu[d] = mu;
    g_scale[d] = rsqrtf(var + 1e-5f) * gamma[d];
}

// ---------------- K3: normalize + edge scatter ----------------
#define NORM_BLOCKS ((NN * DD / 4 + 255) / 256)
#define SCAT_BLOCKS ((EE + 255) / 256)
__global__ void norm_scatter_k(const float* __restrict__ feat, const float* __restrict__ beta,
                               const int* __restrict__ src, const int* __restrict__ dst) {
    int b = blockIdx.x, tid = threadIdx.x;
    if (b < NORM_BLOCKS) {
        int idx = b * 256 + tid;
        if (idx >= NN * DD / 4) return;
        float4 f = ((const float4*)feat)[idx];
        int d = (idx * 4) & (DD - 1);
        float4 o;
        o.x = (f.x - g_mu[d + 0]) * g_scale[d + 0] + beta[d + 0];
        o.y = (f.y - g_mu[d + 1]) * g_scale[d + 1] + beta[d + 1];
        o.z = (f.z - g_mu[d + 2]) * g_scale[d + 2] + beta[d + 2];
        o.w = (f.w - g_mu[d + 3]) * g_scale[d + 3] + beta[d + 3];
        ((float4*)g_X)[idx] = o;
    } else {
        int e = (b - NORM_BLOCKS) * 256 + tid;
        if (e >= EE) return;
        int d = dst[e];
        if ((unsigned)d >= NN) return;
        int slot = atomicAdd(&g_deg[d], 1);
        if (slot < CAP)
            g_keys[(size_t)d * CAP + slot] = ((unsigned long long)e << 32) | (unsigned)src[e];
    }
}

// ---------------- K4: persistent gemm384 (fp16 mma, G2-layout fp16 out) + node sort ----------------
__global__ __launch_bounds__(256) void gemm_sort_k(const float* __restrict__ W,
                                                   const float* __restrict__ bias) {
    extern __shared__ float sm[];
    int tid = threadIdx.x, lane = tid & 31, w = tid >> 5;

    if (blockIdx.x >= GPERS) {
        // ---- node sort: 4 nodes per warp ----
        unsigned long long* buf = (unsigned long long*)sm + w * CAP;
        int base_node = (blockIdx.x - GPERS) * 32 + w * 4;
        for (int q = 0; q < 4; q++) {
            int node = base_node + q;
            if (node >= NN) break;
            int deg = g_deg[node];
            int L = deg < CAP ? deg : CAP;
            if (lane < L)      buf[lane]      = g_keys[(size_t)node * CAP + lane];
            if (lane + 32 < L) buf[lane + 32] = g_keys[(size_t)node * CAP + lane + 32];
            __syncwarp();
            for (int m = 0; m < 2; m++) {
                int idx = lane + 32 * m;
                if (idx < L) {
                    unsigned long long key = buf[idx];
                    int rank = 0;
                    for (int i = 0; i < L; i++) rank += (buf[i] < key);
                    if (rank < MAXDEG)
                        g_neigh[node * MAXDEG + rank] = (int)(unsigned)(key & 0xffffffffull);
                }
            }
            if (lane == 0) {
                int len = deg < MAXDEG ? deg : MAXDEG;
                g_len[node] = len;
                atomicAdd(&g_hist[len], 1);
            }
            __syncwarp();
        }
        return;
    }

    // ---- persistent gemm: W staged once, loop over 32-row chunks ----
    uint32_t* Wh = (uint32_t*)sm;             // 384*64 words
    uint32_t* Ah = Wh + 24576;                // 32*64 words
    int g2 = lane >> 2, t4 = lane & 3;
    int cx = g2 << 2;
    int dbase = w * 16;

    for (int i = tid; i < TD * 64; i += 256) {
        int n = i >> 6, c = i & 63;
        float2 wv = *(const float2*)(W + n * DD + 2 * c);
        Wh[(n << 6) + (c ^ ((n & 7) << 2))] = pack_h2(wv.x, wv.y);
    }
    float bb[3][2][2];
#pragma unroll
    for (int g = 0; g < 3; g++)
#pragma unroll
        for (int dt = 0; dt < 2; dt++) {
            int D0 = g * 128 + dbase + 8 * dt + 2 * t4;
            bb[g][dt][0] = bias[D0];
            bb[g][dt][1] = bias[D0 + 1];
        }
    __syncthreads();

    for (int chunk = blockIdx.x; chunk < GEMM_CHUNKS; chunk += GPERS) {
        int r0b = chunk * 32;
        for (int i = tid; i < 32 * 64; i += 256) {
            int rl = i >> 6, c = i & 63;
            int r = r0b + rl;
            float2 av = (r < NN) ? *(const float2*)(g_X + (size_t)r * DD + 2 * c)
                                 : make_float2(0.f, 0.f);
            Ah[(rl << 6) + (c ^ ((rl & 7) << 2))] = pack_h2(av.x, av.y);
        }
        __syncthreads();

        float cacc[3][2][2][4];
#pragma unroll
        for (int g = 0; g < 3; g++)
#pragma unroll
            for (int mt = 0; mt < 2; mt++)
#pragma unroll
                for (int dt = 0; dt < 2; dt++) {
                    cacc[g][mt][dt][0] = bb[g][dt][0];
                    cacc[g][mt][dt][1] = bb[g][dt][1];
                    cacc[g][mt][dt][2] = bb[g][dt][0];
                    cacc[g][mt][dt][3] = bb[g][dt][1];
                }
#pragma unroll
        for (int kk = 0; kk < 8; kk++) {
            int c0 = kk * 8 + t4;
            int ca = c0 ^ cx, ca4 = (c0 + 4) ^ cx;
            uint32_t am[2][4];
#pragma unroll
            for (int mt = 0; mt < 2; mt++) {
                int r0 = (16 * mt + g2) << 6;
                int r1 = r0 + (8 << 6);
                am[mt][0] = Ah[r0 + ca];
                am[mt][1] = Ah[r1 + ca];
                am[mt][2] = Ah[r0 + ca4];
                am[mt][3] = Ah[r1 + ca4];
            }
            uint32_t bf[3][2][2];
#pragma unroll
            for (int g = 0; g < 3; g++)
#pragma unroll
                for (int dt = 0; dt < 2; dt++) {
                    int nb = (g * 128 + dbase + 8 * dt + g2) << 6;
                    bf[g][dt][0] = Wh[nb + ca];
                    bf[g][dt][1] = Wh[nb + ca4];
                }
#pragma unroll
            for (int g = 0; g < 3; g++)
#pragma unroll
                for (int mt = 0; mt < 2; mt++)
#pragma unroll
                    for (int dt = 0; dt < 2; dt++)
                        mma16(cacc[g][mt][dt], am[mt], bf[g][dt]);
        }

        // store into G2 layout: ((r*8 + w)*4 + t4)*12 + dt*6 + g*2
#pragma unroll
        for (int mt = 0; mt < 2; mt++)
#pragma unroll
            for (int rr = 0; rr < 2; rr++) {
                int r = r0b + 16 * mt + g2 + 8 * rr;
                if (r < NN) {
                    __half* Gp = g_Gh + ((size_t)(r * 8 + w) * 4 + t4) * 12;
#pragma unroll
                    for (int dt = 0; dt < 2; dt++)
#pragma unroll
                        for (int g = 0; g < 3; g++)
                            *(uint32_t*)(Gp + dt * 6 + g * 2) =
                                pack_h2(cacc[g][mt][dt][rr * 2], cacc[g][mt][dt][rr * 2 + 1]);
                }
            }
        __syncthreads();
    }
}

// ---------------- K5: place ----------------
__global__ void place_k() {
    __shared__ int off[MAXDEG + 1];
    int tid = threadIdx.x;
    if (tid == 0) {
        int running = 0;
        for (int l = MAXDEG; l >= 0; l--) { off[l] = running; running += g_hist[l]; }
    }
    __syncthreads();
    int n = blockIdx.x * blockDim.x + tid;
    if (n < NN) {
        int l = g_len[n];
        int pos = off[l] + atomicAdd(&g_cnt[l], 1);
        g_order[pos] = n;
    }
}

// ---------------- K6: GRU via fp16 mma + ldmatrix, 64 nodes/CTA, f16x2 tanh epilogue ----------------
__global__ __launch_bounds__(256, 1) void gru_mma_k(const float* __restrict__ Whh,
                                                    const float* __restrict__ bhh) {
    extern __shared__ float sm[];
    uint32_t* Wh = (uint32_t*)sm;             // 3*128*64 = 24576 words
    uint32_t* Hh = Wh + 24576;                // 2 * 64*64 = 8192 words
    int*   s_s   = (int*)(Hh + 8192);         // [2][64]
    int*   nid_s = s_s + 128;                 // [64]
    int*   len_s = nid_s + 64;                // [64]

    int tid = threadIdx.x, lane = tid & 31, w = tid >> 5;
    int g2 = lane >> 2, t4 = lane & 3;
    int cx = g2 << 2;
    int dbase = w * 16;
    int base = blockIdx.x * GNODES;

    for (int i = tid; i < 3 * 128 * 64; i += 256) {
        int n = i >> 6, c = i & 63;
        float2 wv = *(const float2*)(Whh + n * 128 + 2 * c);
        Wh[(n << 6) + (c ^ ((n & 7) << 2))] = pack_h2(wv.x, wv.y);
    }
    for (int i = tid; i < 2 * GNODES * 64; i += 256) Hh[i] = 0u;
    if (tid < GNODES) {
        int gi = base + tid;
        int nid = (gi < NN) ? g_order[gi] : -1;
        nid_s[tid] = nid;
        len_s[tid] = (nid >= 0) ? g_len[nid] : 0;
    }
    __syncthreads();

    int maxlen = len_s[0];
    int lenR[4][2];
#pragma unroll
    for (int mt = 0; mt < 4; mt++)
#pragma unroll
        for (int rr = 0; rr < 2; rr++)
            lenR[mt][rr] = len_s[16 * mt + g2 + 8 * rr];
    float bb[3][2][2];
#pragma unroll
    for (int g = 0; g < 3; g++)
#pragma unroll
        for (int dt = 0; dt < 2; dt++) {
            int D0 = g * 128 + dbase + 8 * dt + 2 * t4;
            bb[g][dt][0] = bhh[D0];
            bb[g][dt][1] = bhh[D0 + 1];
        }
    float ho[4][2][4];
#pragma unroll
    for (int mt = 0; mt < 4; mt++)
#pragma unroll
        for (int dt = 0; dt < 2; dt++)
#pragma unroll
            for (int c = 0; c < 4; c++) ho[mt][dt][c] = 0.f;

    if (tid < GNODES)
        s_s[tid] = (0 < len_s[tid]) ? g_neigh[nid_s[tid] * MAXDEG] : 0;
    __syncthreads();

    uint32_t WhA = smem_u32(Wh);
    uint32_t HhA = smem_u32(Hh);
    int cxr   = (lane & 7) << 2;
    int kselA = ((lane >> 4) & 1) << 2;
    int kselB = ((lane >> 3) & 1) << 2;
    uint32_t arow = (uint32_t)((lane & 15) << 6);
    uint32_t brow[3];
#pragma unroll
    for (int g = 0; g < 3; g++)
        brow[g] = (uint32_t)((g * 128 + dbase + ((lane >> 4) & 1) * 8 + (lane & 7)) << 6);
    int gsub = (w * 4 + t4) * 12;

    for (int t = 0; t < maxlen; t++) {
        uint32_t HcurA = HhA + (uint32_t)((t & 1) * 4096 * 4);
        uint32_t* Hnxt = Hh + ((t + 1) & 1) * 4096;

        // prefetch next-step src id (consumed at bottom)
        int nxt_s = 0;
        if (tid < GNODES) {
            int tt = t + 1;
            nxt_s = (tt < len_s[tid]) ? g_neigh[nid_s[tid] * MAXDEG + tt] : 0;
        }

        // prefetch ALL G for this step: 3 x LDG.64 per (mt,rr), contiguous 24B
        uint32_t gfu[4][2][6];
#pragma unroll
        for (int mt = 0; mt < 4; mt++)
#pragma unroll
            for (int rr = 0; rr < 2; rr++) {
                int s = s_s[(t & 1) * 64 + 16 * mt + g2 + 8 * rr];
                const uint2* Gp = (const uint2*)(g_Gh + (size_t)s * TD + gsub);
                uint2 v0 = Gp[0], v1 = Gp[1], v2 = Gp[2];
                gfu[mt][rr][0] = v0.x; gfu[mt][rr][1] = v0.y;
                gfu[mt][rr][2] = v1.x; gfu[mt][rr][3] = v1.y;
                gfu[mt][rr][4] = v2.x; gfu[mt][rr][5] = v2.y;
            }

        // accumulators = b_hh
        float cacc[3][4][2][4];
#pragma unroll
        for (int g = 0; g < 3; g++)
#pragma unroll
            for (int mt = 0; mt < 4; mt++)
#pragma unroll
                for (int dt = 0; dt < 2; dt++) {
                    cacc[g][mt][dt][0] = bb[g][dt][0];
                    cacc[g][mt][dt][1] = bb[g][dt][1];
                    cacc[g][mt][dt][2] = bb[g][dt][0];
                    cacc[g][mt][dt][3] = bb[g][dt][1];
                }

        // fp16 mma K-loop with ldmatrix
#pragma unroll
        for (int kk = 0; kk < 8; kk++) {
            uint32_t woffA = (uint32_t)((kk * 8 + kselA) ^ cxr);
            uint32_t woffB = (uint32_t)((kk * 8 + kselB) ^ cxr);
            uint32_t am[4][4];
#pragma unroll
            for (int mt = 0; mt < 4; mt++)
                ldsm4(am[mt], HcurA + ((arow + (uint32_t)(mt * 1024) + woffA) << 2));
            uint32_t bf[3][4];
#pragma unroll
            for (int g = 0; g < 3; g++)
                ldsm4(bf[g], WhA + ((brow[g] + woffB) << 2));
#pragma unroll
            for (int g = 0; g < 3; g++)
#pragma unroll
                for (int mt = 0; mt < 4; mt++) {
                    mma16(cacc[g][mt][0], am[mt], &bf[g][0]);
                    mma16(cacc[g][mt][1], am[mt], &bf[g][2]);
                }
        }

        // ---- epilogue: fp32 preactivations, f16x2 tanh (half the MUFU) ----
#pragma unroll
        for (int mt = 0; mt < 4; mt++)
#pragma unroll
            for (int rr = 0; rr < 2; rr++) {
                bool act = (t < lenR[mt][rr]);
                int R = 16 * mt + g2 + 8 * rr;
                int c0 = rr * 2;
#pragma unroll
                for (int dt = 0; dt < 2; dt++) {
                    float2 vr = unpack_h2(gfu[mt][rr][dt * 3 + 0]);
                    float2 vz = unpack_h2(gfu[mt][rr][dt * 3 + 1]);
                    float2 vn = unpack_h2(gfu[mt][rr][dt * 3 + 2]);
                    float pr0 = vr.x + cacc[0][mt][dt][c0];
                    float pr1 = vr.y + cacc[0][mt][dt][c0 + 1];
                    float pz0 = vz.x + cacc[1][mt][dt][c0];
                    float pz1 = vz.y + cacc[1][mt][dt][c0 + 1];
                    float2 fr = unpack_h2(h2tanh(pack_h2(0.5f * pr0, 0.5f * pr1)));
                    float2 fz = unpack_h2(h2tanh(pack_h2(0.5f * pz0, 0.5f * pz1)));
                    float r0 = fmaf(fr.x, 0.5f, 0.5f), r1 = fmaf(fr.y, 0.5f, 0.5f);
                    float z0 = fmaf(fz.x, 0.5f, 0.5f), z1 = fmaf(fz.y, 0.5f, 0.5f);
                    float pn0 = vn.x + r0 * cacc[2][mt][dt][c0];
                    float pn1 = vn.y + r1 * cacc[2][mt][dt][c0 + 1];
                    float2 fn = unpack_h2(h2tanh(pack_h2(pn0, pn1)));
                    float h0 = fn.x + z0 * (ho[mt][dt][c0]     - fn.x);
                    float h1 = fn.y + z1 * (ho[mt][dt][c0 + 1] - fn.y);
                    if (act) { ho[mt][dt][c0] = h0; ho[mt][dt][c0 + 1] = h1; }
                    int D0 = dbase + 8 * dt + 2 * t4;
                    Hnxt[(R << 6) + ((D0 >> 1) ^ cx)] =
                        pack_h2(ho[mt][dt][c0], ho[mt][dt][c0 + 1]);
                }
            }

        if (tid < GNODES) s_s[((t + 1) & 1) * 64 + tid] = nxt_s;
        __syncthreads();
    }

    // final hidden to gmem
#pragma unroll
    for (int mt = 0; mt < 4; mt++)
#pragma unroll
        for (int rr = 0; rr < 2; rr++) {
            int nid = nid_s[16 * mt + g2 + 8 * rr];
            if (nid >= 0) {
#pragma unroll
                for (int dt = 0; dt < 2; dt++) {
                    int D0 = dbase + 8 * dt + 2 * t4;
                    *(float2*)&g_Hn[(size_t)nid * DD + D0] =
                        make_float2(ho[mt][dt][rr * 2], ho[mt][dt][rr * 2 + 1]);
                }
            }
        }
}

// ---------------- K7: persistent out = [X|Hn] @ [W_self|W_neigh]^T (fp16, K=256) ----------------
__global__ __launch_bounds__(256) void out_k(const float* __restrict__ Wself,
                                             const float* __restrict__ Wneigh,
                                             float* __restrict__ out) {
    extern __shared__ float sm[];
    uint32_t* Wh = (uint32_t*)sm;             // 128*128 words
    uint32_t* Ah = Wh + 16384;                // 32*128 words
    int tid = threadIdx.x, lane = tid & 31, w = tid >> 5;
    int g2 = lane >> 2, t4 = lane & 3;
    int cx = g2 << 2;
    int dbase = w * 16;

    for (int i = tid; i < DD * 128; i += 256) {
        int o = i >> 7, c = i & 127;
        int k = 2 * c;
        float2 wv = (k < 128) ? *(const float2*)(Wself + o * DD + k)
                              : *(const float2*)(Wneigh + o * DD + (k - 128));
        Wh[(o << 7) + (c ^ ((o & 7) << 2))] = pack_h2(wv.x, wv.y);
    }
    __syncthreads();

    for (int chunk = blockIdx.x; chunk < GEMM_CHUNKS; chunk += GPERS) {
        int r0b = chunk * 32;
        for (int i = tid; i < 32 * 128; i += 256) {
            int rl = i >> 7, c = i & 127;
            int r = r0b + rl;
            float2 av = make_float2(0.f, 0.f);
            if (r < NN) {
                int k = 2 * c;
                av = (k < 128) ? *(const float2*)(g_X + (size_t)r * DD + k)
                               : *(const float2*)(g_Hn + (size_t)r * DD + (k - 128));
            }
            Ah[(rl << 7) + (c ^ ((rl & 7) << 2))] = pack_h2(av.x, av.y);
        }
        __syncthreads();

        float cacc[2][2][4];
#pragma unroll
        for (int mt = 0; mt < 2; mt++)
#pragma unroll
            for (int dt = 0; dt < 2; dt++)
#pragma unroll
                for (int c = 0; c < 4; c++) cacc[mt][dt][c] = 0.f;

#pragma unroll
        for (int kk = 0; kk < 16; kk++) {
            int c0 = kk * 8 + t4;
            int ca = c0 ^ cx, ca4 = (c0 + 4) ^ cx;
            uint32_t am[2][4];
#pragma unroll
            for (int mt = 0; mt < 2; mt++) {
                int r0 = (16 * mt + g2) << 7;
                int r1 = r0 + (8 << 7);
                am[mt][0] = Ah[r0 + ca];
                am[mt][1] = Ah[r1 + ca];
                am[mt][2] = Ah[r0 + ca4];
                am[mt][3] = Ah[r1 + ca4];
            }
            uint32_t bf[2][2];
#pragma unroll
            for (int dt = 0; dt < 2; dt++) {
                int nb = (dbase + 8 * dt + g2) << 7;
                bf[dt][0] = Wh[nb + ca];
                bf[dt][1] = Wh[nb + ca4];
            }
#pragma unroll
            for (int mt = 0; mt < 2; mt++)
#pragma unroll
                for (int dt = 0; dt < 2; dt++)
                    mma16(cacc[mt][dt], am[mt], bf[dt]);
        }

#pragma unroll
        for (int mt = 0; mt < 2; mt++)
#pragma unroll
            for (int rr = 0; rr < 2; rr++) {
                int r = r0b + 16 * mt + g2 + 8 * rr;
                if (r < NN) {
#pragma unroll
                    for (int dt = 0; dt < 2; dt++) {
                        int D0 = dbase + 8 * dt + 2 * t4;
                        *(float2*)&out[(size_t)r * DD + D0] =
                            make_float2(cacc[mt][dt][rr * 2], cacc[mt][dt][rr * 2 + 1]);
                    }
                }
            }
        __syncthreads();
    }
}

// ---------------- launch ----------------
extern "C" void kernel_launch(void* const* d_in, const int* in_sizes, int n_in,
                              void* d_out, int out_size) {
    const float* feat   = (const float*)d_in[0];
    const int*   src    = (const int*)d_in[1];
    const int*   dst    = (const int*)d_in[2];
    const float* gamma  = (const float*)d_in[3];
    const float* beta   = (const float*)d_in[4];
    const float* W_ih   = (const float*)d_in[5];
    const float* W_hh   = (const float*)d_in[6];
    const float* b_ih   = (const float*)d_in[7];
    const float* b_hh   = (const float*)d_in[8];
    const float* W_self = (const float*)d_in[9];
    const float* W_neigh= (const float*)d_in[10];
    float* out = (float*)d_out;

    const int smA = (24576 + 2048) * 4;
    const int smG = (24576 + 8192) * 4 + 256 * 4;
    const int smO = (16384 + 4096) * 4;
    cudaFuncSetAttribute(gemm_sort_k, cudaFuncAttributeMaxDynamicSharedMemorySize, smA);
    cudaFuncSetAttribute(gru_mma_k,   cudaFuncAttributeMaxDynamicSharedMemorySize, smG);
    cudaFuncSetAttribute(out_k,       cudaFuncAttributeMaxDynamicSharedMemorySize, smO);

    bn_clear_k<<<BN_BLOCKS + (NN + 127) / 128, 128>>>(feat);
    bn_final_k<<<1, DD>>>(gamma);
    norm_scatter_k<<<NORM_BLOCKS + SCAT_BLOCKS, 256>>>(feat, beta, src, dst);
    gemm_sort_k<<<GPERS + SORT_BLOCKS, 256, smA>>>(W_ih, b_ih);
    place_k<<<(NN + 255) / 256, 256>>>();
    gru_mma_k<<<GRU_BLOCKS, 256, smG>>>(W_hh, b_hh);
    out_k<<<GPERS, 256, smO>>>(W_self, W_neigh, out);
}

// round 17
// speedup vs baseline: 1.0832x; 1.0832x over previous
#include <cuda_runtime.h>
#include <cuda_fp16.h>
#include <cstdint>

#define NN 50000
#define DD 128
#define EE 800000
#define TD 384
#define MAXDEG 48
#define CAP 64
#define BN_BLOCKS 512
#define BN_CHUNK 98
#define GNODES 64
#define GRU_BLOCKS ((NN + GNODES - 1) / GNODES)   // 782
#define GEMM_CHUNKS ((NN + 31) / 32)              // 1563
#define GPERS 148                                  // 1 persistent gemm block / SM
#define OPERS 296
#define SORT_BLOCKS ((NN + 31) / 32)              // 1563

// ---------------- scratch (static device memory; no allocations) ----------------
__device__ float  g_X[NN * DD];
// G2 layout: [node][slice(8)][t4(4)][dt(2)][gate(3)][2 halves] = 384 halves/node
__device__ __half g_Gh[(size_t)NN * TD];
__device__ float  g_Hn[NN * DD];
__device__ float  g_part[2 * BN_BLOCKS * DD];
__device__ float  g_mu[DD];
__device__ float  g_scale[DD];
__device__ int    g_deg[NN];
__device__ unsigned long long g_keys[(size_t)NN * CAP];
__device__ int    g_neigh[NN * MAXDEG];
__device__ int    g_len[NN];
__device__ int    g_order[NN];
__device__ int    g_hist[MAXDEG + 1];
__device__ int    g_cnt[MAXDEG + 1];

// ---------------- helpers ----------------
__device__ __forceinline__ void mma16(float* c, const uint32_t* a, const uint32_t* b) {
    asm volatile(
        "mma.sync.aligned.m16n8k16.row.col.f32.f16.f16.f32 "
        "{%0,%1,%2,%3},{%4,%5,%6,%7},{%8,%9},{%0,%1,%2,%3};"
        : "+f"(c[0]), "+f"(c[1]), "+f"(c[2]), "+f"(c[3])
        : "r"(a[0]), "r"(a[1]), "r"(a[2]), "r"(a[3]), "r"(b[0]), "r"(b[1]));
}
__device__ __forceinline__ void ldsm4(uint32_t* r, uint32_t addr) {
    asm volatile("ldmatrix.sync.aligned.m8n8.x4.shared.b16 {%0,%1,%2,%3}, [%4];"
                 : "=r"(r[0]), "=r"(r[1]), "=r"(r[2]), "=r"(r[3]) : "r"(addr));
}
__device__ __forceinline__ uint32_t smem_u32(const void* p) {
    uint32_t a;
    asm("{ .reg .u64 t; cvta.to.shared.u64 t, %1; cvt.u32.u64 %0, t; }" : "=r"(a) : "l"(p));
    return a;
}
__device__ __forceinline__ float fast_tanh(float x) {
    float t;
    asm("tanh.approx.f32 %0, %1;" : "=f"(t) : "f"(x));
    return t;
}
__device__ __forceinline__ float fast_sigmoid(float x) {
    return 0.5f * fast_tanh(0.5f * x) + 0.5f;
}
__device__ __forceinline__ uint32_t pack_h2(float a, float b) {
    __half2 h = __floats2half2_rn(a, b);
    return *(uint32_t*)&h;
}
__device__ __forceinline__ float2 unpack_h2(uint32_t u) {
    return __half22float2(*(__half2*)&u);
}

// ---------------- K1: BN partial sums + clear counters ----------------
__global__ void bn_clear_k(const float* __restrict__ feat) {
    int b = blockIdx.x, tid = threadIdx.x;
    if (b < BN_BLOCKS) {
        int r0 = b * BN_CHUNK;
        int r1 = r0 + BN_CHUNK; if (r1 > NN) r1 = NN;
        float s = 0.f, ss = 0.f;
        for (int r = r0; r < r1; r++) {
            float v = feat[(size_t)r * DD + tid];
            s += v; ss += v * v;
        }
        g_part[b * DD + tid] = s;
        g_part[BN_BLOCKS * DD + b * DD + tid] = ss;
    } else {
        int i = (b - BN_BLOCKS) * 128 + tid;
        if (i < NN) g_deg[i] = 0;
        if (i <= MAXDEG) { g_hist[i] = 0; g_cnt[i] = 0; }
    }
}

// ---------------- K2: BN finalize ----------------
__global__ void bn_final_k(const float* __restrict__ gamma) {
    int d = threadIdx.x;
    float s = 0.f, ss = 0.f;
    for (int b = 0; b < BN_BLOCKS; b++) {
        s  += g_part[b * DD + d];
        ss += g_part[BN_BLOCKS * DD + b * DD + d];
    }
    float mu = s / (float)NN;
    float var = ss / (float)NN - mu * mu;
    g_mu[d] = mu;
    g_scale[d] = rsqrtf(var + 1e-5f) * gamma[d];
}

// ---------------- K3: normalize + edge scatter ----------------
#define NORM_BLOCKS ((NN * DD / 4 + 255) / 256)
#define SCAT_BLOCKS ((EE + 255) / 256)
__global__ void norm_scatter_k(const float* __restrict__ feat, const float* __restrict__ beta,
                               const int* __restrict__ src, const int* __restrict__ dst) {
    int b = blockIdx.x, tid = threadIdx.x;
    if (b < NORM_BLOCKS) {
        int idx = b * 256 + tid;
        if (idx >= NN * DD / 4) return;
        float4 f = ((const float4*)feat)[idx];
        int d = (idx * 4) & (DD - 1);
        float4 o;
        o.x = (f.x - g_mu[d + 0]) * g_scale[d + 0] + beta[d + 0];
        o.y = (f.y - g_mu[d + 1]) * g_scale[d + 1] + beta[d + 1];
        o.z = (f.z - g_mu[d + 2]) * g_scale[d + 2] + beta[d + 2];
        o.w = (f.w - g_mu[d + 3]) * g_scale[d + 3] + beta[d + 3];
        ((float4*)g_X)[idx] = o;
    } else {
        int e = (b - NORM_BLOCKS) * 256 + tid;
        if (e >= EE) return;
        int d = dst[e];
        if ((unsigned)d >= NN) return;
        int slot = atomicAdd(&g_deg[d], 1);
        if (slot < CAP)
            g_keys[(size_t)d * CAP + slot] = ((unsigned long long)e << 32) | (unsigned)src[e];
    }
}

// ---------------- K4: persistent gemm384 (148 blocks, 1/SM) + concurrent node sort ----------------
// Grid order: gemm blocks first (fill one slot/SM), sort blocks stream through the 2nd slot.
__global__ __launch_bounds__(256) void gemm_sort_k(const float* __restrict__ W,
                                                   const float* __restrict__ bias) {
    extern __shared__ float sm[];
    int tid = threadIdx.x, lane = tid & 31, w = tid >> 5;

    if (blockIdx.x >= GPERS) {
        // ---- node sort: 4 nodes per warp ----
        unsigned long long* buf = (unsigned long long*)sm + w * CAP;
        int base_node = (blockIdx.x - GPERS) * 32 + w * 4;
        for (int q = 0; q < 4; q++) {
            int node = base_node + q;
            if (node >= NN) break;
            int deg = g_deg[node];
            int L = deg < CAP ? deg : CAP;
            if (lane < L)      buf[lane]      = g_keys[(size_t)node * CAP + lane];
            if (lane + 32 < L) buf[lane + 32] = g_keys[(size_t)node * CAP + lane + 32];
            __syncwarp();
            for (int m = 0; m < 2; m++) {
                int idx = lane + 32 * m;
                if (idx < L) {
                    unsigned long long key = buf[idx];
                    int rank = 0;
                    for (int i = 0; i < L; i++) rank += (buf[i] < key);
                    if (rank < MAXDEG)
                        g_neigh[node * MAXDEG + rank] = (int)(unsigned)(key & 0xffffffffull);
                }
            }
            if (lane == 0) {
                int len = deg < MAXDEG ? deg : MAXDEG;
                g_len[node] = len;
                atomicAdd(&g_hist[len], 1);
            }
            __syncwarp();
        }
        return;
    }

    // ---- persistent gemm: W staged once, loop over 32-row chunks ----
    uint32_t* Wh = (uint32_t*)sm;             // 384*64 words
    uint32_t* Ah = Wh + 24576;                // 32*64 words
    int g2 = lane >> 2, t4 = lane & 3;
    int cx = g2 << 2;
    int dbase = w * 16;

    for (int i = tid; i < TD * 64; i += 256) {
        int n = i >> 6, c = i & 63;
        float2 wv = *(const float2*)(W + n * DD + 2 * c);
        Wh[(n << 6) + (c ^ ((n & 7) << 2))] = pack_h2(wv.x, wv.y);
    }
    float bb[3][2][2];
#pragma unroll
    for (int g = 0; g < 3; g++)
#pragma unroll
        for (int dt = 0; dt < 2; dt++) {
            int D0 = g * 128 + dbase + 8 * dt + 2 * t4;
            bb[g][dt][0] = bias[D0];
            bb[g][dt][1] = bias[D0 + 1];
        }
    __syncthreads();

    for (int chunk = blockIdx.x; chunk < GEMM_CHUNKS; chunk += GPERS) {
        int r0b = chunk * 32;
        for (int i = tid; i < 32 * 64; i += 256) {
            int rl = i >> 6, c = i & 63;
            int r = r0b + rl;
            float2 av = (r < NN) ? *(const float2*)(g_X + (size_t)r * DD + 2 * c)
                                 : make_float2(0.f, 0.f);
            Ah[(rl << 6) + (c ^ ((rl & 7) << 2))] = pack_h2(av.x, av.y);
        }
        __syncthreads();

        float cacc[3][2][2][4];
#pragma unroll
        for (int g = 0; g < 3; g++)
#pragma unroll
            for (int mt = 0; mt < 2; mt++)
#pragma unroll
                for (int dt = 0; dt < 2; dt++) {
                    cacc[g][mt][dt][0] = bb[g][dt][0];
                    cacc[g][mt][dt][1] = bb[g][dt][1];
                    cacc[g][mt][dt][2] = bb[g][dt][0];
                    cacc[g][mt][dt][3] = bb[g][dt][1];
                }
#pragma unroll
        for (int kk = 0; kk < 8; kk++) {
            int c0 = kk * 8 + t4;
            int ca = c0 ^ cx, ca4 = (c0 + 4) ^ cx;
            uint32_t am[2][4];
#pragma unroll
            for (int mt = 0; mt < 2; mt++) {
                int r0 = (16 * mt + g2) << 6;
                int r1 = r0 + (8 << 6);
                am[mt][0] = Ah[r0 + ca];
                am[mt][1] = Ah[r1 + ca];
                am[mt][2] = Ah[r0 + ca4];
                am[mt][3] = Ah[r1 + ca4];
            }
            uint32_t bf[3][2][2];
#pragma unroll
            for (int g = 0; g < 3; g++)
#pragma unroll
                for (int dt = 0; dt < 2; dt++) {
                    int nb = (g * 128 + dbase + 8 * dt + g2) << 6;
                    bf[g][dt][0] = Wh[nb + ca];
                    bf[g][dt][1] = Wh[nb + ca4];
                }
#pragma unroll
            for (int g = 0; g < 3; g++)
#pragma unroll
                for (int mt = 0; mt < 2; mt++)
#pragma unroll
                    for (int dt = 0; dt < 2; dt++)
                        mma16(cacc[g][mt][dt], am[mt], bf[g][dt]);
        }

        // store into G2 layout via 3x uint2: ((r*8 + w)*4 + t4)*12 + dt*6 + g*2
#pragma unroll
        for (int mt = 0; mt < 2; mt++)
#pragma unroll
            for (int rr = 0; rr < 2; rr++) {
                int r = r0b + 16 * mt + g2 + 8 * rr;
                if (r < NN) {
                    uint2* Gp = (uint2*)(g_Gh + ((size_t)(r * 8 + w) * 4 + t4) * 12);
                    uint32_t wd[6];
#pragma unroll
                    for (int dt = 0; dt < 2; dt++)
#pragma unroll
                        for (int g = 0; g < 3; g++)
                            wd[dt * 3 + g] =
                                pack_h2(cacc[g][mt][dt][rr * 2], cacc[g][mt][dt][rr * 2 + 1]);
                    Gp[0] = make_uint2(wd[0], wd[1]);
                    Gp[1] = make_uint2(wd[2], wd[3]);
                    Gp[2] = make_uint2(wd[4], wd[5]);
                }
            }
        __syncthreads();
    }
}

// ---------------- K5: place ----------------
__global__ void place_k() {
    __shared__ int off[MAXDEG + 1];
    int tid = threadIdx.x;
    if (tid == 0) {
        int running = 0;
        for (int l = MAXDEG; l >= 0; l--) { off[l] = running; running += g_hist[l]; }
    }
    __syncthreads();
    int n = blockIdx.x * blockDim.x + tid;
    if (n < NN) {
        int l = g_len[n];
        int pos = off[l] + atomicAdd(&g_cnt[l], 1);
        g_order[pos] = n;
    }
}

// ---------------- K6: GRU via fp16 mma + ldmatrix, 64 nodes/CTA (R14 epilogue) ----------------
__global__ __launch_bounds__(256, 1) void gru_mma_k(const float* __restrict__ Whh,
                                                    const float* __restrict__ bhh) {
    extern __shared__ float sm[];
    uint32_t* Wh = (uint32_t*)sm;             // 3*128*64 = 24576 words
    uint32_t* Hh = Wh + 24576;                // 2 * 64*64 = 8192 words
    int*   s_s   = (int*)(Hh + 8192);         // [2][64]
    int*   nid_s = s_s + 128;                 // [64]
    int*   len_s = nid_s + 64;                // [64]

    int tid = threadIdx.x, lane = tid & 31, w = tid >> 5;
    int g2 = lane >> 2, t4 = lane & 3;
    int cx = g2 << 2;
    int dbase = w * 16;
    int base = blockIdx.x * GNODES;

    for (int i = tid; i < 3 * 128 * 64; i += 256) {
        int n = i >> 6, c = i & 63;
        float2 wv = *(const float2*)(Whh + n * 128 + 2 * c);
        Wh[(n << 6) + (c ^ ((n & 7) << 2))] = pack_h2(wv.x, wv.y);
    }
    for (int i = tid; i < 2 * GNODES * 64; i += 256) Hh[i] = 0u;
    if (tid < GNODES) {
        int gi = base + tid;
        int nid = (gi < NN) ? g_order[gi] : -1;
        nid_s[tid] = nid;
        len_s[tid] = (nid >= 0) ? g_len[nid] : 0;
    }
    __syncthreads();

    int maxlen = len_s[0];
    int lenR[4][2];
#pragma unroll
    for (int mt = 0; mt < 4; mt++)
#pragma unroll
        for (int rr = 0; rr < 2; rr++)
            lenR[mt][rr] = len_s[16 * mt + g2 + 8 * rr];
    float bb[3][2][2];
#pragma unroll
    for (int g = 0; g < 3; g++)
#pragma unroll
        for (int dt = 0; dt < 2; dt++) {
            int D0 = g * 128 + dbase + 8 * dt + 2 * t4;
            bb[g][dt][0] = bhh[D0];
            bb[g][dt][1] = bhh[D0 + 1];
        }
    float ho[4][2][4];
#pragma unroll
    for (int mt = 0; mt < 4; mt++)
#pragma unroll
        for (int dt = 0; dt < 2; dt++)
#pragma unroll
            for (int c = 0; c < 4; c++) ho[mt][dt][c] = 0.f;

    if (tid < GNODES)
        s_s[tid] = (0 < len_s[tid]) ? g_neigh[nid_s[tid] * MAXDEG] : 0;
    __syncthreads();

    uint32_t WhA = smem_u32(Wh);
    uint32_t HhA = smem_u32(Hh);
    int cxr   = (lane & 7) << 2;
    int kselA = ((lane >> 4) & 1) << 2;
    int kselB = ((lane >> 3) & 1) << 2;
    uint32_t arow = (uint32_t)((lane & 15) << 6);
    uint32_t brow[3];
#pragma unroll
    for (int g = 0; g < 3; g++)
        brow[g] = (uint32_t)((g * 128 + dbase + ((lane >> 4) & 1) * 8 + (lane & 7)) << 6);
    int gsub = (w * 4 + t4) * 12;

    for (int t = 0; t < maxlen; t++) {
        uint32_t HcurA = HhA + (uint32_t)((t & 1) * 4096 * 4);
        uint32_t* Hnxt = Hh + ((t + 1) & 1) * 4096;

        // prefetch next-step src id (consumed at bottom)
        int nxt_s = 0;
        if (tid < GNODES) {
            int tt = t + 1;
            nxt_s = (tt < len_s[tid]) ? g_neigh[nid_s[tid] * MAXDEG + tt] : 0;
        }

        // prefetch ALL G for this step: 3 x LDG.64 per (mt,rr), contiguous 24B
        uint32_t gfu[4][2][6];
#pragma unroll
        for (int mt = 0; mt < 4; mt++)
#pragma unroll
            for (int rr = 0; rr < 2; rr++) {
                int s = s_s[(t & 1) * 64 + 16 * mt + g2 + 8 * rr];
                const uint2* Gp = (const uint2*)(g_Gh + (size_t)s * TD + gsub);
                uint2 v0 = Gp[0], v1 = Gp[1], v2 = Gp[2];
                gfu[mt][rr][0] = v0.x; gfu[mt][rr][1] = v0.y;
                gfu[mt][rr][2] = v1.x; gfu[mt][rr][3] = v1.y;
                gfu[mt][rr][4] = v2.x; gfu[mt][rr][5] = v2.y;
            }

        // accumulators = b_hh
        float cacc[3][4][2][4];
#pragma unroll
        for (int g = 0; g < 3; g++)
#pragma unroll
            for (int mt = 0; mt < 4; mt++)
#pragma unroll
                for (int dt = 0; dt < 2; dt++) {
                    cacc[g][mt][dt][0] = bb[g][dt][0];
                    cacc[g][mt][dt][1] = bb[g][dt][1];
                    cacc[g][mt][dt][2] = bb[g][dt][0];
                    cacc[g][mt][dt][3] = bb[g][dt][1];
                }

        // fp16 mma K-loop with ldmatrix
#pragma unroll
        for (int kk = 0; kk < 8; kk++) {
            uint32_t woffA = (uint32_t)((kk * 8 + kselA) ^ cxr);
            uint32_t woffB = (uint32_t)((kk * 8 + kselB) ^ cxr);
            uint32_t am[4][4];
#pragma unroll
            for (int mt = 0; mt < 4; mt++)
                ldsm4(am[mt], HcurA + ((arow + (uint32_t)(mt * 1024) + woffA) << 2));
            uint32_t bf[3][4];
#pragma unroll
            for (int g = 0; g < 3; g++)
                ldsm4(bf[g], WhA + ((brow[g] + woffB) << 2));
#pragma unroll
            for (int g = 0; g < 3; g++)
#pragma unroll
                for (int mt = 0; mt < 4; mt++) {
                    mma16(cacc[g][mt][0], am[mt], &bf[g][0]);
                    mma16(cacc[g][mt][1], am[mt], &bf[g][2]);
                }
        }

        // epilogue (R14 numerics)
#pragma unroll
        for (int mt = 0; mt < 4; mt++)
#pragma unroll
            for (int rr = 0; rr < 2; rr++) {
                bool act = (t < lenR[mt][rr]);
                int R = 16 * mt + g2 + 8 * rr;
#pragma unroll
                for (int dt = 0; dt < 2; dt++) {
                    float2 vr = unpack_h2(gfu[mt][rr][dt * 3 + 0]);
                    float2 vz = unpack_h2(gfu[mt][rr][dt * 3 + 1]);
                    float2 vn = unpack_h2(gfu[mt][rr][dt * 3 + 2]);
                    int D0 = dbase + 8 * dt + 2 * t4;
#pragma unroll
                    for (int e = 0; e < 2; e++) {
                        int c = rr * 2 + e;
                        float gr = e ? vr.y : vr.x;
                        float gz = e ? vz.y : vz.x;
                        float gn = e ? vn.y : vn.x;
                        float r  = fast_sigmoid(gr + cacc[0][mt][dt][c]);
                        float z  = fast_sigmoid(gz + cacc[1][mt][dt][c]);
                        float nl = fast_tanh(gn + r * cacc[2][mt][dt][c]);
                        float hnew = (1.f - z) * nl + z * ho[mt][dt][c];
                        if (act) ho[mt][dt][c] = hnew;
                    }
                    Hnxt[(R << 6) + ((D0 >> 1) ^ cx)] =
                        pack_h2(ho[mt][dt][rr * 2], ho[mt][dt][rr * 2 + 1]);
                }
            }

        if (tid < GNODES) s_s[((t + 1) & 1) * 64 + tid] = nxt_s;
        __syncthreads();
    }

    // final hidden to gmem
#pragma unroll
    for (int mt = 0; mt < 4; mt++)
#pragma unroll
        for (int rr = 0; rr < 2; rr++) {
            int nid = nid_s[16 * mt + g2 + 8 * rr];
            if (nid >= 0) {
#pragma unroll
                for (int dt = 0; dt < 2; dt++) {
                    int D0 = dbase + 8 * dt + 2 * t4;
                    *(float2*)&g_Hn[(size_t)nid * DD + D0] =
                        make_float2(ho[mt][dt][rr * 2], ho[mt][dt][rr * 2 + 1]);
                }
            }
        }
}

// ---------------- K7: persistent out = [X|Hn] @ [W_self|W_neigh]^T (fp16, K=256) ----------------
__global__ __launch_bounds__(256) void out_k(const float* __restrict__ Wself,
                                             const float* __restrict__ Wneigh,
                                             float* __restrict__ out) {
    extern __shared__ float sm[];
    uint32_t* Wh = (uint32_t*)sm;             // 128*128 words
    uint32_t* Ah = Wh + 16384;                // 32*128 words
    int tid = threadIdx.x, lane = tid & 31, w = tid >> 5;
    int g2 = lane >> 2, t4 = lane & 3;
    int cx = g2 << 2;
    int dbase = w * 16;

    for (int i = tid; i < DD * 128; i += 256) {
        int o = i >> 7, c = i & 127;
        int k = 2 * c;
        float2 wv = (k < 128) ? *(const float2*)(Wself + o * DD + k)
                              : *(const float2*)(Wneigh + o * DD + (k - 128));
        Wh[(o << 7) + (c ^ ((o & 7) << 2))] = pack_h2(wv.x, wv.y);
    }
    __syncthreads();

    for (int chunk = blockIdx.x; chunk < GEMM_CHUNKS; chunk += OPERS) {
        int r0b = chunk * 32;
        for (int i = tid; i < 32 * 128; i += 256) {
            int rl = i >> 7, c = i & 127;
            int r = r0b + rl;
            float2 av = make_float2(0.f, 0.f);
            if (r < NN) {
                int k = 2 * c;
                av = (k < 128) ? *(const float2*)(g_X + (size_t)r * DD + k)
                               : *(const float2*)(g_Hn + (size_t)r * DD + (k - 128));
            }
            Ah[(rl << 7) + (c ^ ((rl & 7) << 2))] = pack_h2(av.x, av.y);
        }
        __syncthreads();

        float cacc[2][2][4];
#pragma unroll
        for (int mt = 0; mt < 2; mt++)
#pragma unroll
            for (int dt = 0; dt < 2; dt++)
#pragma unroll
                for (int c = 0; c < 4; c++) cacc[mt][dt][c] = 0.f;

#pragma unroll
        for (int kk = 0; kk < 16; kk++) {
            int c0 = kk * 8 + t4;
            int ca = c0 ^ cx, ca4 = (c0 + 4) ^ cx;
            uint32_t am[2][4];
#pragma unroll
            for (int mt = 0; mt < 2; mt++) {
                int r0 = (16 * mt + g2) << 7;
                int r1 = r0 + (8 << 7);
                am[mt][0] = Ah[r0 + ca];
                am[mt][1] = Ah[r1 + ca];
                am[mt][2] = Ah[r0 + ca4];
                am[mt][3] = Ah[r1 + ca4];
            }
            uint32_t bf[2][2];
#pragma unroll
            for (int dt = 0; dt < 2; dt++) {
                int nb = (dbase + 8 * dt + g2) << 7;
                bf[dt][0] = Wh[nb + ca];
                bf[dt][1] = Wh[nb + ca4];
            }
#pragma unroll
            for (int mt = 0; mt < 2; mt++)
#pragma unroll
                for (int dt = 0; dt < 2; dt++)
                    mma16(cacc[mt][dt], am[mt], bf[dt]);
        }

#pragma unroll
        for (int mt = 0; mt < 2; mt++)
#pragma unroll
            for (int rr = 0; rr < 2; rr++) {
                int r = r0b + 16 * mt + g2 + 8 * rr;
                if (r < NN) {
#pragma unroll
                    for (int dt = 0; dt < 2; dt++) {
                        int D0 = dbase + 8 * dt + 2 * t4;
                        *(float2*)&out[(size_t)r * DD + D0] =
                            make_float2(cacc[mt][dt][rr * 2], cacc[mt][dt][rr * 2 + 1]);
                    }
                }
            }
        __syncthreads();
    }
}

// ---------------- launch ----------------
extern "C" void kernel_launch(void* const* d_in, const int* in_sizes, int n_in,
                              void* d_out, int out_size) {
    const float* feat   = (const float*)d_in[0];
    const int*   src    = (const int*)d_in[1];
    const int*   dst    = (const int*)d_in[2];
    const float* gamma  = (const float*)d_in[3];
    const float* beta   = (const float*)d_in[4];
    const float* W_ih   = (const float*)d_in[5];
    const float* W_hh   = (const float*)d_in[6];
    const float* b_ih   = (const float*)d_in[7];
    const float* b_hh   = (const float*)d_in[8];
    const float* W_self = (const float*)d_in[9];
    const float* W_neigh= (const float*)d_in[10];
    float* out = (float*)d_out;

    const int smA = (24576 + 2048) * 4;
    const int smG = (24576 + 8192) * 4 + 256 * 4;
    const int smO = (16384 + 4096) * 4;
    cudaFuncSetAttribute(gemm_sort_k, cudaFuncAttributeMaxDynamicSharedMemorySize, smA);
    cudaFuncSetAttribute(gru_mma_k,   cudaFuncAttributeMaxDynamicSharedMemorySize, smG);
    cudaFuncSetAttribute(out_k,       cudaFuncAttributeMaxDynamicSharedMemorySize, smO);

    bn_clear_k<<<BN_BLOCKS + (NN + 127) / 128, 128>>>(feat);
    bn_final_k<<<1, DD>>>(gamma);
    norm_scatter_k<<<NORM_BLOCKS + SCAT_BLOCKS, 256>>>(feat, beta, src, dst);
    gemm_sort_k<<<GPERS + SORT_BLOCKS, 256, smA>>>(W_ih, b_ih);
    place_k<<<(NN + 255) / 256, 256>>>();
    gru_mma_k<<<GRU_BLOCKS, 256, smG>>>(W_hh, b_hh);
    out_k<<<OPERS, 256, smO>>>(W_self, W_neigh, out);
}